// round 8
// baseline (speedup 1.0000x reference)
#include <cuda_runtime.h>
#include <cstdint>

// ---------------------------------------------------------------------------
// TT embedding:  VOC = 100^3,  EMB = 4*4*8 = 128,  RANK = 16
//   out[tok, n1*32+n2*8+n3] = sum_{r1,r2} core0[i1,n1,r1]*core1[r1,i2,n2,r2]*core2[r2,i3,n3]
// idx = i1*10000 + i2*100 + i3; idx==0 (PAD) -> zero row.
//
// Kernel 1 : G01[i12][row*16+r2] = sum_r1 core0*core1  (10.2MB, L2-resident)
//            + fused pack of core2 into C2P[i3][j][q][n3] (51KB, L1-resident)
//            where r2 = 8q + j  (j in [0,8), q in {0,1}).
// Kernel 2 : warp/token. Lane (row,q) loads ONLY its r2-half of the G row
//            (2x coalesced LDG.128, no duplication -> 16 wf), C2P layout puts
//            both q-halves in one 128B line (16 wf), partials merged with one
//            end-of-chain butterfly. Reg-capped to 32 for 100% occupancy.
// ---------------------------------------------------------------------------

#define VOC_LL 1000000ULL

__device__ float g_G01[10000 * 256];
__device__ float g_C2P[100 * 128];   // [i3][j][q][n3] = core2[8q+j][i3][n3]

// ---- packed fp32x2 helpers (sm_103a) --------------------------------------
__device__ __forceinline__ unsigned long long f32x2_fma(
    unsigned long long a, unsigned long long b, unsigned long long c)
{
    unsigned long long d;
    asm("fma.rn.f32x2 %0, %1, %2, %3;" : "=l"(d) : "l"(a), "l"(b), "l"(c));
    return d;
}
__device__ __forceinline__ unsigned long long f32x2_add(
    unsigned long long a, unsigned long long b)
{
    unsigned long long d;
    asm("add.rn.f32x2 %0, %1, %2;" : "=l"(d) : "l"(a), "l"(b));
    return d;
}
__device__ __forceinline__ unsigned long long f32x2_bcast(float x)
{
    unsigned long long d;
    asm("mov.b64 %0, {%1, %1};" : "=l"(d) : "f"(x));
    return d;
}
__device__ __forceinline__ unsigned long long shfl_xor_u64(unsigned long long v, int m)
{
    unsigned int lo = (unsigned int)v, hi = (unsigned int)(v >> 32);
    lo = __shfl_xor_sync(0xffffffffu, lo, m);
    hi = __shfl_xor_sync(0xffffffffu, hi, m);
    return ((unsigned long long)hi << 32) | lo;
}

// ---------------------------------------------------------------------------
// Kernel 1: G01 precompute + fused core2 pack.
// grid = (100, 21), block = 128.
//   y < 20 : G01 for i2 = blockIdx.x, i1 in [5y, 5y+5)
//   y == 20: pack core2 for i3 = blockIdx.x
// core0: (1,100,4,16)  elem (i1,n1,r1)    @ i1*64 + n1*16 + r1
// core1: (16,100,4,16) elem (r1,i2,n2,r2) @ r1*6400 + i2*64 + n2*16 + r2
// core2: (16,100,8)    elem (r2,i3,n3)    @ r2*800 + i3*8 + n3
// ---------------------------------------------------------------------------
__global__ void __launch_bounds__(128) tt_precompute(
    const float* __restrict__ core0,
    const float* __restrict__ core1,
    const float* __restrict__ core2)
{
    const int i2 = blockIdx.x;
    const int g  = blockIdx.y;
    const int p  = threadIdx.x;

    if (g == 20) {
        // pack: C2P[i3*128 + p],  p = j*16 + q*8 + n3
        const int i3 = i2;
        const int j  = p >> 4;
        const int q  = (p >> 3) & 1;
        const int n3 = p & 7;
        g_C2P[i3 * 128 + p] = core2[(8 * q + j) * 800 + i3 * 8 + n3];
        return;
    }

    __shared__ float Bs[1024];   // core1 slice for this i2: [r1][n2*16+r2]
    __shared__ float As[320];    // core0 slices for 5 i1: [q][n1*16+r1]

    #pragma unroll
    for (int j = p; j < 1024; j += 128)
        Bs[j] = core1[(j >> 6) * 6400 + i2 * 64 + (j & 63)];
    #pragma unroll
    for (int j = p; j < 320; j += 128)
        As[j] = core0[g * 320 + j];
    __syncthreads();

    const int n1 = p >> 5;         // constant per warp -> As broadcast
    const int rp = (p & 31) * 2;   // rest pair start (n2*16+r2)

    unsigned long long b2[16];
    #pragma unroll
    for (int r1 = 0; r1 < 16; r1++)
        b2[r1] = *(const unsigned long long*)&Bs[r1 * 64 + rp];

    #pragma unroll
    for (int q = 0; q < 5; q++) {
        unsigned long long acc = 0;
        #pragma unroll
        for (int r1 = 0; r1 < 16; r1++)
            acc = f32x2_fma(f32x2_bcast(As[q * 64 + n1 * 16 + r1]), b2[r1], acc);
        const int i1 = g * 5 + q;
        *(unsigned long long*)&g_G01[((size_t)(i1 * 100 + i2)) * 256 + p * 2] = acc;
    }
}

// ---------------------------------------------------------------------------
// Kernel 2: gather.  1 warp per token, 4 outputs/lane.
// lane: row = lane>>1 (n1*4+n2), q = lane&1 (r2-half owned & n3-half kept).
// G: lane loads granules 2*lane, 2*lane+1 (fully coalesced, no duplication)
//    = gr[r2] for r2 in [8q, 8q+8) of its row.
// C: for j in [0,8): 2x LDG.128 at i3*512 + j*64 + q*32 + {0,16}
//    -> warp touches ONE 128B line per instruction.
// Lane accumulates partials for all 8 n3 over its 8 r2's; one butterfly
// (lane^1) merges the halves; lane stores n3 in [4q, 4q+4).
// ---------------------------------------------------------------------------
__global__ void __launch_bounds__(256, 8) tt_gather(
    const void*  __restrict__ xraw,
    float*       __restrict__ out,
    int n_tok)
{
    const int t    = threadIdx.x;
    const int lane = t & 31;
    const int tok  = blockIdx.x * 8 + (t >> 5);
    if (tok >= n_tok) return;

    // --- index dtype autodetect: one 16B load, 2 samples.
    // int32 layout misreads as u64 >= VOC unless the paired hi-word is 0
    // (p ~ 1e-6 per sample; both zero ~ 1e-12). int64 values are all < VOC.
    const ulonglong2 ds = *(const ulonglong2*)xraw;
    const bool is64 = (ds.x < VOC_LL) && (ds.y < VOC_LL);

    const long long idxll = is64 ? ((const long long*)xraw)[tok]
                                 : (long long)((const int*)xraw)[tok];
    const unsigned int iv  = (unsigned int)idxll;      // < 1e6
    const unsigned int i3  = iv % 100u;
    const unsigned int i12 = iv / 100u;

    const int q = lane & 1;

    // own r2-half of the G row (coalesced: granules 2*lane, 2*lane+1)
    const float4* G = (const float4*)(g_G01 + (size_t)i12 * 256);
    const float4 ga = G[2 * lane];       // r2 = 8q+0..3
    const float4 gb = G[2 * lane + 1];   // r2 = 8q+4..7

    // C2P base for (i3, q)
    const char* cb = (const char*)g_C2P + (size_t)i3 * 512 + q * 32;

    // partials for all 8 n3: acc0=(n3 0,1) acc1=(2,3) acc2=(4,5) acc3=(6,7)
    unsigned long long acc0 = 0, acc1 = 0, acc2 = 0, acc3 = 0;
    #pragma unroll
    for (int j = 0; j < 8; j++) {
        const ulonglong2 c0 = *(const ulonglong2*)(cb + j * 64);        // n3 0..3
        const ulonglong2 c1 = *(const ulonglong2*)(cb + j * 64 + 16);   // n3 4..7
        float gs;
        switch (j) {
            case 0: gs = ga.x; break;  case 1: gs = ga.y; break;
            case 2: gs = ga.z; break;  case 3: gs = ga.w; break;
            case 4: gs = gb.x; break;  case 5: gs = gb.y; break;
            case 6: gs = gb.z; break;  default: gs = gb.w; break;
        }
        const unsigned long long gg = f32x2_bcast(gs);
        acc0 = f32x2_fma(gg, c0.x, acc0);
        acc1 = f32x2_fma(gg, c0.y, acc1);
        acc2 = f32x2_fma(gg, c1.x, acc2);
        acc3 = f32x2_fma(gg, c1.y, acc3);
    }

    // single butterfly: keep n3 [4q,4q+4), exchange the other half
    const unsigned long long keep0 = q ? acc2 : acc0;
    const unsigned long long keep1 = q ? acc3 : acc1;
    const unsigned long long send0 = q ? acc0 : acc2;
    const unsigned long long send1 = q ? acc1 : acc3;
    const unsigned long long recv0 = shfl_xor_u64(send0, 1);
    const unsigned long long recv1 = shfl_xor_u64(send1, 1);

    ulonglong2 res;
    res.x = f32x2_add(keep0, recv0);
    res.y = f32x2_add(keep1, recv1);
    if (iv == 0) { res.x = 0; res.y = 0; }   // PAD row

    const int row = lane >> 1;
    *(ulonglong2*)(out + (size_t)tok * 128 + row * 8 + q * 4) = res;
}

// ---------------------------------------------------------------------------
extern "C" void kernel_launch(void* const* d_in, const int* in_sizes, int n_in,
                              void* d_out, int out_size)
{
    const void*  x     = d_in[0];
    const float* core0 = (const float*)d_in[1];
    const float* core1 = (const float*)d_in[2];
    const float* core2 = (const float*)d_in[3];
    float*       out   = (float*)d_out;

    const int n_tok = in_sizes[0];   // 32768

    tt_precompute<<<dim3(100, 21), 128>>>(core0, core1, core2);
    tt_gather<<<(n_tok + 7) / 8, 256>>>(x, out, n_tok);
}

// round 9
// speedup vs baseline: 1.2000x; 1.2000x over previous
#include <cuda_runtime.h>
#include <cstdint>

// ---------------------------------------------------------------------------
// TT embedding:  VOC = 100^3,  EMB = 4*4*8 = 128,  RANK = 16
//   out[tok, n1*32+n2*8+n3] = sum_{r1,r2} core0[i1,n1,r1]*core1[r1,i2,n2,r2]*core2[r2,i3,n3]
// idx = i1*10000 + i2*100 + i3; idx==0 (PAD) -> zero row.
//
// Kernel 1 : G01[i12][row*16+r2] = sum_r1 core0*core1  (10.2MB, L2-resident)
//            + fused pack of core2 into C2Q[i3][j][c][n3] (51KB), r2 = 4c+j.
// Kernel 2 : warp/token, minimal-wavefront layout:
//   G: 2x contiguous LDG.128 (4 lines each -> 8 wf total).  Lane L owns
//      r2-quad c=L&3 of rows k=L>>2 and k+8.
//   C: 8 instr, each warp-wide inside ONE 128B line (8 wf).
//   Partials reduced across the 4 quad-lanes with a 2-round reduce-scatter
//   (12 SHFL.32), then 2x 256B-contiguous u64 stores (4 wf).
// ---------------------------------------------------------------------------

#define VOC_LL 1000000ULL

__device__ float g_G01[10000 * 256];
__device__ float g_C2Q[100 * 128];   // [i3][j][c][n3] = core2[4c+j][i3][n3]

// ---- packed fp32x2 helpers (sm_103a) --------------------------------------
__device__ __forceinline__ unsigned long long f32x2_fma(
    unsigned long long a, unsigned long long b, unsigned long long c)
{
    unsigned long long d;
    asm("fma.rn.f32x2 %0, %1, %2, %3;" : "=l"(d) : "l"(a), "l"(b), "l"(c));
    return d;
}
__device__ __forceinline__ unsigned long long f32x2_add(
    unsigned long long a, unsigned long long b)
{
    unsigned long long d;
    asm("add.rn.f32x2 %0, %1, %2;" : "=l"(d) : "l"(a), "l"(b));
    return d;
}
__device__ __forceinline__ unsigned long long f32x2_bcast(float x)
{
    unsigned long long d;
    asm("mov.b64 %0, {%1, %1};" : "=l"(d) : "f"(x));
    return d;
}
__device__ __forceinline__ unsigned long long shfl_xor_u64(unsigned long long v, int m)
{
    unsigned int lo = (unsigned int)v, hi = (unsigned int)(v >> 32);
    lo = __shfl_xor_sync(0xffffffffu, lo, m);
    hi = __shfl_xor_sync(0xffffffffu, hi, m);
    return ((unsigned long long)hi << 32) | lo;
}

// ---------------------------------------------------------------------------
// Kernel 1: G01 precompute + fused core2 pack.
// grid = (100, 21), block = 128.
//   y < 20 : G01 for i2 = blockIdx.x, i1 in [5y, 5y+5)
//   y == 20: pack core2 for i3 = blockIdx.x
// core0: (1,100,4,16)  elem (i1,n1,r1)    @ i1*64 + n1*16 + r1
// core1: (16,100,4,16) elem (r1,i2,n2,r2) @ r1*6400 + i2*64 + n2*16 + r2
// core2: (16,100,8)    elem (r2,i3,n3)    @ r2*800 + i3*8 + n3
// ---------------------------------------------------------------------------
__global__ void __launch_bounds__(128) tt_precompute(
    const float* __restrict__ core0,
    const float* __restrict__ core1,
    const float* __restrict__ core2)
{
    const int i2 = blockIdx.x;
    const int g  = blockIdx.y;
    const int p  = threadIdx.x;

    if (g == 20) {
        // pack: C2Q[i3*128 + p],  p = j*32 + c*8 + n3,  r2 = 4c + j
        const int i3 = i2;
        const int j  = p >> 5;
        const int c  = (p >> 3) & 3;
        const int n3 = p & 7;
        g_C2Q[i3 * 128 + p] = core2[(4 * c + j) * 800 + i3 * 8 + n3];
        return;
    }

    __shared__ float Bs[1024];   // core1 slice for this i2: [r1][n2*16+r2]
    __shared__ float As[320];    // core0 slices for 5 i1: [q][n1*16+r1]

    #pragma unroll
    for (int j = p; j < 1024; j += 128)
        Bs[j] = core1[(j >> 6) * 6400 + i2 * 64 + (j & 63)];
    #pragma unroll
    for (int j = p; j < 320; j += 128)
        As[j] = core0[g * 320 + j];
    __syncthreads();

    const int n1 = p >> 5;         // constant per warp -> As broadcast
    const int rp = (p & 31) * 2;   // rest pair start (n2*16+r2)

    unsigned long long b2[16];
    #pragma unroll
    for (int r1 = 0; r1 < 16; r1++)
        b2[r1] = *(const unsigned long long*)&Bs[r1 * 64 + rp];

    #pragma unroll
    for (int q = 0; q < 5; q++) {
        unsigned long long acc = 0;
        #pragma unroll
        for (int r1 = 0; r1 < 16; r1++)
            acc = f32x2_fma(f32x2_bcast(As[q * 64 + n1 * 16 + r1]), b2[r1], acc);
        const int i1 = g * 5 + q;
        *(unsigned long long*)&g_G01[((size_t)(i1 * 100 + i2)) * 256 + p * 2] = acc;
    }
}

// ---------------------------------------------------------------------------
// Kernel 2: gather.  1 warp per token, 4 outputs/lane.
// lane L: k = L>>2 (row pair k, k+8), c = L&3 (r2-quad [4c,4c+4)).
// ---------------------------------------------------------------------------
__global__ void __launch_bounds__(256, 6) tt_gather(
    const void*  __restrict__ xraw,
    float*       __restrict__ out,
    int n_tok)
{
    const int t    = threadIdx.x;
    const int lane = t & 31;
    const int tok  = blockIdx.x * 8 + (t >> 5);
    if (tok >= n_tok) return;

    // --- index dtype autodetect: one 16B broadcast load, 2 samples.
    // int32 data misread as u64 is >= VOC unless the paired hi word is 0
    // (p ~ 1e-12 for both samples); int64 data is always < VOC.
    const ulonglong2 ds = *(const ulonglong2*)xraw;
    const bool is64 = (ds.x < VOC_LL) && (ds.y < VOC_LL);

    const long long idxll = is64 ? ((const long long*)xraw)[tok]
                                 : (long long)((const int*)xraw)[tok];
    const unsigned int iv  = (unsigned int)idxll;      // < 1e6
    const unsigned int i3  = iv % 100u;
    const unsigned int i12 = iv / 100u;

    const int k = lane >> 2;
    const int c = lane & 3;

    // G: 2 contiguous LDG.128 (512B each -> 4 lines per instruction)
    // ga = row k,   r2 [4c,4c+4);  gb = row k+8, same quad.
    const float4* Gp = (const float4*)(g_G01 + (size_t)i12 * 256);
    const float4 ga = Gp[lane];
    const float4 gb = Gp[lane + 32];
    const float gA[4] = { ga.x, ga.y, ga.z, ga.w };
    const float gB[4] = { gb.x, gb.y, gb.z, gb.w };

    // C2Q base: lane reads, for j=0..3, 32B at i3*512 + j*128 + c*32
    // (per instruction the warp stays inside one 128B line).
    const char* cb = (const char*)g_C2Q + (size_t)i3 * 512 + c * 32;

    // partials: rows {k, k+8} x n3-pairs {01,23,45,67} over my 4 r2's
    unsigned long long aA0 = 0, aA1 = 0, aA2 = 0, aA3 = 0;
    unsigned long long aB0 = 0, aB1 = 0, aB2 = 0, aB3 = 0;
    #pragma unroll
    for (int j = 0; j < 4; j++) {
        const ulonglong2 c0 = *(const ulonglong2*)(cb + j * 128);        // n3 0..3
        const ulonglong2 c1 = *(const ulonglong2*)(cb + j * 128 + 16);   // n3 4..7
        const unsigned long long ggA = f32x2_bcast(gA[j]);
        const unsigned long long ggB = f32x2_bcast(gB[j]);
        aA0 = f32x2_fma(ggA, c0.x, aA0);
        aA1 = f32x2_fma(ggA, c0.y, aA1);
        aA2 = f32x2_fma(ggA, c1.x, aA2);
        aA3 = f32x2_fma(ggA, c1.y, aA3);
        aB0 = f32x2_fma(ggB, c0.x, aB0);
        aB1 = f32x2_fma(ggB, c0.y, aB1);
        aB2 = f32x2_fma(ggB, c1.x, aB2);
        aB3 = f32x2_fma(ggB, c1.y, aB3);
    }

    // reduce-scatter across the 4 quad-lanes (same k, c = 0..3).
    const int b1 = c & 1;        // round 1: keep n3 half [4*b1, 4*b1+4)
    const int b2 = (c >> 1) & 1; // round 2: keep n3 pair  4*b1 + 2*b2

    // round 1 (xor 1)
    unsigned long long kA0 = b1 ? aA2 : aA0, kA1 = b1 ? aA3 : aA1;
    unsigned long long sA0 = b1 ? aA0 : aA2, sA1 = b1 ? aA1 : aA3;
    unsigned long long kB0 = b1 ? aB2 : aB0, kB1 = b1 ? aB3 : aB1;
    unsigned long long sB0 = b1 ? aB0 : aB2, sB1 = b1 ? aB1 : aB3;
    kA0 = f32x2_add(kA0, shfl_xor_u64(sA0, 1));
    kA1 = f32x2_add(kA1, shfl_xor_u64(sA1, 1));
    kB0 = f32x2_add(kB0, shfl_xor_u64(sB0, 1));
    kB1 = f32x2_add(kB1, shfl_xor_u64(sB1, 1));

    // round 2 (xor 2)
    unsigned long long kA = b2 ? kA1 : kA0;
    unsigned long long sA = b2 ? kA0 : kA1;
    unsigned long long kB = b2 ? kB1 : kB0;
    unsigned long long sB = b2 ? kB0 : kB1;
    kA = f32x2_add(kA, shfl_xor_u64(sA, 2));
    kB = f32x2_add(kB, shfl_xor_u64(sB, 2));

    if (iv == 0) { kA = 0; kB = 0; }   // PAD row

    // store: rows k and k+8, n3 pair starting at 4*b1 + 2*b2
    const int n3off = 4 * b1 + 2 * b2;
    float* obase = out + (size_t)tok * 128;
    *(unsigned long long*)(obase + k * 8 + n3off)        = kA;
    *(unsigned long long*)(obase + (k + 8) * 8 + n3off)  = kB;
}

// ---------------------------------------------------------------------------
extern "C" void kernel_launch(void* const* d_in, const int* in_sizes, int n_in,
                              void* d_out, int out_size)
{
    const void*  x     = d_in[0];
    const float* core0 = (const float*)d_in[1];
    const float* core1 = (const float*)d_in[2];
    const float* core2 = (const float*)d_in[3];
    float*       out   = (float*)d_out;

    const int n_tok = in_sizes[0];   // 32768

    tt_precompute<<<dim3(100, 21), 128>>>(core0, core1, core2);
    tt_gather<<<(n_tok + 7) / 8, 256>>>(x, out, n_tok);
}

// round 10
// speedup vs baseline: 1.2020x; 1.0017x over previous
#include <cuda_runtime.h>
#include <cstdint>

// ---------------------------------------------------------------------------
// TT embedding:  VOC = 100^3,  EMB = 4*4*8 = 128,  RANK = 16
//   out[tok, n1*32+n2*8+n3] = sum_{r1,r2} core0[i1,n1,r1]*core1[r1,i2,n2,r2]*core2[r2,i3,n3]
// idx = i1*10000 + i2*100 + i3; idx==0 (PAD) -> zero row.
//
// Kernel 1 : G01[i12][row*16+r2] = sum_r1 core0*core1  (10.2MB, L2-resident)
//            + fused pack of core2 into C2Q[i3][j][c][n3] (51KB), r2 = 4c+j.
// Kernel 2 : warp/token, minimal-wavefront layout:
//   G: 2x contiguous LDG.128 (4 lines each -> 8 wf).  Lane L owns r2-quad
//      c=L&3 of rows k=L>>2 and k+8.
//   C: 8 instr, each warp-wide inside ONE 128B line (8 wf), with per-lane
//      ADDRESS-PERMUTED n3-half order (b1=c&1) so round 1 of the reduce
//      needs no selects.
//   Reduce-scatter: round 1 = pure shfl+add (0 SEL); round 2 = 8 SEL.
// ---------------------------------------------------------------------------

#define VOC_LL 1000000ULL

__device__ float g_G01[10000 * 256];
__device__ float g_C2Q[100 * 128];   // [i3][j][c][n3] = core2[4c+j][i3][n3]

// ---- packed fp32x2 helpers (sm_103a) --------------------------------------
__device__ __forceinline__ unsigned long long f32x2_fma(
    unsigned long long a, unsigned long long b, unsigned long long c)
{
    unsigned long long d;
    asm("fma.rn.f32x2 %0, %1, %2, %3;" : "=l"(d) : "l"(a), "l"(b), "l"(c));
    return d;
}
__device__ __forceinline__ unsigned long long f32x2_add(
    unsigned long long a, unsigned long long b)
{
    unsigned long long d;
    asm("add.rn.f32x2 %0, %1, %2;" : "=l"(d) : "l"(a), "l"(b));
    return d;
}
__device__ __forceinline__ unsigned long long f32x2_bcast(float x)
{
    unsigned long long d;
    asm("mov.b64 %0, {%1, %1};" : "=l"(d) : "f"(x));
    return d;
}
__device__ __forceinline__ unsigned long long shfl_xor_u64(unsigned long long v, int m)
{
    unsigned int lo = (unsigned int)v, hi = (unsigned int)(v >> 32);
    lo = __shfl_xor_sync(0xffffffffu, lo, m);
    hi = __shfl_xor_sync(0xffffffffu, hi, m);
    return ((unsigned long long)hi << 32) | lo;
}

// ---------------------------------------------------------------------------
// Kernel 1: G01 precompute + fused core2 pack.
// grid = (100, 21), block = 128.
//   y < 20 : G01 for i2 = blockIdx.x, i1 in [5y, 5y+5)
//   y == 20: pack core2 for i3 = blockIdx.x
// core0: (1,100,4,16)  elem (i1,n1,r1)    @ i1*64 + n1*16 + r1
// core1: (16,100,4,16) elem (r1,i2,n2,r2) @ r1*6400 + i2*64 + n2*16 + r2
// core2: (16,100,8)    elem (r2,i3,n3)    @ r2*800 + i3*8 + n3
// ---------------------------------------------------------------------------
__global__ void __launch_bounds__(128) tt_precompute(
    const float* __restrict__ core0,
    const float* __restrict__ core1,
    const float* __restrict__ core2)
{
    const int i2 = blockIdx.x;
    const int g  = blockIdx.y;
    const int p  = threadIdx.x;

    if (g == 20) {
        // pack: C2Q[i3*128 + p],  p = j*32 + c*8 + n3,  r2 = 4c + j
        const int i3 = i2;
        const int j  = p >> 5;
        const int c  = (p >> 3) & 3;
        const int n3 = p & 7;
        g_C2Q[i3 * 128 + p] = core2[(4 * c + j) * 800 + i3 * 8 + n3];
        return;
    }

    __shared__ float Bs[1024];   // core1 slice for this i2: [r1][n2*16+r2]
    __shared__ float As[320];    // core0 slices for 5 i1: [q][n1*16+r1]

    #pragma unroll
    for (int j = p; j < 1024; j += 128)
        Bs[j] = core1[(j >> 6) * 6400 + i2 * 64 + (j & 63)];
    #pragma unroll
    for (int j = p; j < 320; j += 128)
        As[j] = core0[g * 320 + j];
    __syncthreads();

    const int n1 = p >> 5;         // constant per warp -> As broadcast
    const int rp = (p & 31) * 2;   // rest pair start (n2*16+r2)

    unsigned long long b2[16];
    #pragma unroll
    for (int r1 = 0; r1 < 16; r1++)
        b2[r1] = *(const unsigned long long*)&Bs[r1 * 64 + rp];

    #pragma unroll
    for (int q = 0; q < 5; q++) {
        unsigned long long acc = 0;
        #pragma unroll
        for (int r1 = 0; r1 < 16; r1++)
            acc = f32x2_fma(f32x2_bcast(As[q * 64 + n1 * 16 + r1]), b2[r1], acc);
        const int i1 = g * 5 + q;
        *(unsigned long long*)&g_G01[((size_t)(i1 * 100 + i2)) * 256 + p * 2] = acc;
    }
}

// ---------------------------------------------------------------------------
// Kernel 2: gather.  1 warp per token, 4 outputs/lane.
// lane L: k = L>>2 (rows k, k+8), c = L&3 (r2-quad [4c,4c+4)),
//         b1 = c&1 (n3-half kept), b2 = c>>1 (n3-pair kept within half).
// ---------------------------------------------------------------------------
__global__ void __launch_bounds__(256, 6) tt_gather(
    const void*  __restrict__ xraw,
    float*       __restrict__ out,
    int n_tok)
{
    const int t    = threadIdx.x;
    const int lane = t & 31;
    const int tok  = blockIdx.x * 8 + (t >> 5);
    if (tok >= n_tok) return;

    // --- index dtype autodetect: one 16B broadcast load, 2 samples.
    // int32 data misread as u64 is >= VOC unless the paired hi word is 0
    // (p ~ 1e-12 for both samples); int64 data is always < VOC.
    const ulonglong2 ds = *(const ulonglong2*)xraw;
    const bool is64 = (ds.x < VOC_LL) && (ds.y < VOC_LL);

    const long long idxll = is64 ? ((const long long*)xraw)[tok]
                                 : (long long)((const int*)xraw)[tok];
    const unsigned int iv  = (unsigned int)idxll;      // < 1e6
    const unsigned int i3  = iv % 100u;
    const unsigned int i12 = iv / 100u;

    const int k  = lane >> 2;
    const int c  = lane & 3;
    const int b1 = c & 1;
    const int b2 = (c >> 1) & 1;

    // G: 2 contiguous LDG.128 (512B each -> 4 lines per instruction)
    // ga = row k, r2 [4c,4c+4);  gb = row k+8, same quad.
    const float4* __restrict__ Gp = (const float4*)(g_G01 + (size_t)i12 * 256);
    const float4 ga = Gp[lane];
    const float4 gb = Gp[lane + 32];
    const float gA[4] = { ga.x, ga.y, ga.z, ga.w };
    const float gB[4] = { gb.x, gb.y, gb.z, gb.w };

    // C2Q, address-permuted: cb0 -> the n3-half this lane KEEPS (b1),
    // cb1 -> the half it will send.  Per instruction the warp still stays
    // inside one 128B line (permute only toggles +-16B within the line).
    const char* __restrict__ cbase =
        (const char*)g_C2Q + (size_t)i3 * 512 + c * 32;
    const char* cb0 = cbase + 16 * b1;
    const char* cb1 = cbase + 16 * (1 - b1);

    // partials: rows {k, k+8}; acc0/acc1 = kept half (pairs 2b1, 2b1+1),
    // acc2/acc3 = other half.
    unsigned long long aA0 = 0, aA1 = 0, aA2 = 0, aA3 = 0;
    unsigned long long aB0 = 0, aB1 = 0, aB2 = 0, aB3 = 0;
    #pragma unroll
    for (int j = 0; j < 4; j++) {
        const ulonglong2 cK = *(const ulonglong2*)(cb0 + j * 128);  // kept half
        const ulonglong2 cS = *(const ulonglong2*)(cb1 + j * 128);  // send half
        const unsigned long long ggA = f32x2_bcast(gA[j]);
        const unsigned long long ggB = f32x2_bcast(gB[j]);
        aA0 = f32x2_fma(ggA, cK.x, aA0);
        aA1 = f32x2_fma(ggA, cK.y, aA1);
        aA2 = f32x2_fma(ggA, cS.x, aA2);
        aA3 = f32x2_fma(ggA, cS.y, aA3);
        aB0 = f32x2_fma(ggB, cK.x, aB0);
        aB1 = f32x2_fma(ggB, cK.y, aB1);
        aB2 = f32x2_fma(ggB, cS.x, aB2);
        aB3 = f32x2_fma(ggB, cS.y, aB3);
    }

    // round 1 (xor 1): partner's acc2/acc3 are MY half -> no selects.
    const unsigned long long k0A = f32x2_add(aA0, shfl_xor_u64(aA2, 1));
    const unsigned long long k1A = f32x2_add(aA1, shfl_xor_u64(aA3, 1));
    const unsigned long long k0B = f32x2_add(aB0, shfl_xor_u64(aB2, 1));
    const unsigned long long k1B = f32x2_add(aB1, shfl_xor_u64(aB3, 1));

    // round 2 (xor 2): keep pair 2b1+b2, send the other pair.
    const unsigned long long kkA = b2 ? k1A : k0A;
    const unsigned long long ssA = b2 ? k0A : k1A;
    const unsigned long long kkB = b2 ? k1B : k0B;
    const unsigned long long ssB = b2 ? k0B : k1B;
    unsigned long long fA = f32x2_add(kkA, shfl_xor_u64(ssA, 2));
    unsigned long long fB = f32x2_add(kkB, shfl_xor_u64(ssB, 2));

    if (iv == 0) { fA = 0; fB = 0; }   // PAD row

    // store: rows k and k+8, n3 pair starting at 4b1 + 2b2
    const int n3off = 4 * b1 + 2 * b2;
    float* obase = out + (size_t)tok * 128;
    *(unsigned long long*)(obase + k * 8 + n3off)       = fA;
    *(unsigned long long*)(obase + (k + 8) * 8 + n3off) = fB;
}

// ---------------------------------------------------------------------------
extern "C" void kernel_launch(void* const* d_in, const int* in_sizes, int n_in,
                              void* d_out, int out_size)
{
    const void*  x     = d_in[0];
    const float* core0 = (const float*)d_in[1];
    const float* core1 = (const float*)d_in[2];
    const float* core2 = (const float*)d_in[3];
    float*       out   = (float*)d_out;

    const int n_tok = in_sizes[0];   // 32768

    tt_precompute<<<dim3(100, 21), 128>>>(core0, core1, core2);
    tt_gather<<<(n_tok + 7) / 8, 256>>>(x, out, n_tok);
}